// round 7
// baseline (speedup 1.0000x reference)
#include <cuda_runtime.h>

static constexpr int NENT = 50000;
static constexpr int CC   = 128;      // channels
static constexpr int C4   = 32;       // float4 per row
static constexpr int NRELM1 = 10;     // N_REL - 1
static constexpr int MAXE = 1700000;  // >= N_EDGES

// Scratch (no cudaMalloc allowed)
__device__ __align__(16) float g_emb [(size_t)NENT * CC];
__device__ __align__(16) float g_emb2[(size_t)NENT * CC];
__device__ int      g_hist[NENT];
__device__ int      g_cur[NENT];
__device__ int      g_off[NENT + 1];
__device__ unsigned g_packed[MAXE];   // tail | (type-1)<<20, head-sorted

// ---------------------------------------------------------------------------
__global__ void k_init() {
    const int stride = gridDim.x * blockDim.x;
    for (int j = blockIdx.x * blockDim.x + threadIdx.x; j < NENT; j += stride) {
        g_hist[j] = 0;
        g_cur[j]  = 0;
    }
}

__global__ void k_hist(const int* __restrict__ head, int E) {
    int i = blockIdx.x * blockDim.x + threadIdx.x;
    if (i < E) atomicAdd(&g_hist[head[i]], 1);
}

// Exclusive prefix scan of g_hist -> g_off (single block, 1024 threads)
__global__ void k_scan() {
    __shared__ int warpsum[32];
    __shared__ int warpoff[32];
    __shared__ int s_run;
    const int tid  = threadIdx.x;
    const int lane = tid & 31;
    const int wid  = tid >> 5;
    if (tid == 0) s_run = 0;
    __syncthreads();

    for (int base = 0; base < NENT; base += 1024) {
        int v = (base + tid < NENT) ? g_hist[base + tid] : 0;
        int x = v;
        #pragma unroll
        for (int o = 1; o < 32; o <<= 1) {
            int y = __shfl_up_sync(0xffffffffu, x, o);
            if (lane >= o) x += y;
        }
        if (lane == 31) warpsum[wid] = x;
        __syncthreads();
        if (wid == 0) {
            int w = warpsum[lane];
            int xi = w;
            #pragma unroll
            for (int o = 1; o < 32; o <<= 1) {
                int y = __shfl_up_sync(0xffffffffu, xi, o);
                if (lane >= o) xi += y;
            }
            warpoff[lane] = xi - w;   // exclusive warp offset
        }
        __syncthreads();
        int incl = x + warpoff[wid];
        int run  = s_run;
        if (base + tid < NENT) g_off[base + tid] = run + incl - v;
        __syncthreads();
        if (tid == 1023) s_run = run + incl;
        __syncthreads();
    }
    if (threadIdx.x == 0) g_off[NENT] = s_run;
}

__global__ void k_scatter(const int* __restrict__ head,
                          const int* __restrict__ tail,
                          const int* __restrict__ etype, int E) {
    int i = blockIdx.x * blockDim.x + threadIdx.x;
    if (i < E) {
        int h   = head[i];
        int pos = g_off[h] + atomicAdd(&g_cur[h], 1);
        g_packed[pos] = (unsigned)tail[i] | ((unsigned)(etype[i] - 1) << 20);
    }
}

// ---------------------------------------------------------------------------
// Fused hop: warp per head entity.
//   acc = sum_{edges of head} emb_in[tail] * w[type]   (registers)
//   n   = acc / max(||acc||, eps)    (scale-invariant: degree divide skipped)
//   emb_out = n (if non-null);  out = resid_in + n
// NOTE: emb_in and emb_out must be DISTINCT buffers (cross-row race otherwise).
// ---------------------------------------------------------------------------
__global__ void k_hop(const float4* __restrict__ emb_in,
                      const float4* __restrict__ resid_in,
                      float4*       __restrict__ out4,
                      float4*       __restrict__ emb_out,   // may be null
                      const float4* __restrict__ w4) {
    __shared__ float4 sw[NRELM1 * C4];   // 5 KB relation table
    for (int i = threadIdx.x; i < NRELM1 * C4; i += blockDim.x) sw[i] = w4[i];
    __syncthreads();

    const int warp = (blockIdx.x * blockDim.x + threadIdx.x) >> 5;
    const int lane = threadIdx.x & 31;
    if (warp >= NENT) return;

    const int s = g_off[warp];
    const int e = g_off[warp + 1];

    float4 acc = make_float4(0.f, 0.f, 0.f, 0.f);
    for (int base = s; base < e; base += 32) {
        const int n = min(32, e - base);
        unsigned p = (base + lane < e) ? g_packed[base + lane] : 0u;
        for (int k = 0; k < n; k++) {
            const unsigned pk = __shfl_sync(0xffffffffu, p, k);
            const int t  = (int)(pk & 0xFFFFFu);
            const int ty = (int)(pk >> 20);
            float4 ev = emb_in[(long)t * C4 + lane];
            float4 r  = sw[ty * C4 + lane];
            acc.x += ev.x * r.x;
            acc.y += ev.y * r.y;
            acc.z += ev.z * r.z;
            acc.w += ev.w * r.w;
        }
    }

    float ss = acc.x * acc.x + acc.y * acc.y + acc.z * acc.z + acc.w * acc.w;
    #pragma unroll
    for (int o = 16; o > 0; o >>= 1)
        ss += __shfl_xor_sync(0xffffffffu, ss, o);

    const float inv = 1.0f / fmaxf(sqrtf(ss), 1e-12f);
    const float4 n4 = make_float4(acc.x * inv, acc.y * inv,
                                  acc.z * inv, acc.w * inv);

    const long idx = (long)warp * C4 + lane;
    if (emb_out) emb_out[idx] = n4;
    float4 b = resid_in[idx];
    out4[idx] = make_float4(b.x + n4.x, b.y + n4.y, b.z + n4.z, b.w + n4.w);
}

// ---------------------------------------------------------------------------
extern "C" void kernel_launch(void* const* d_in, const int* in_sizes, int n_in,
                              void* d_out, int out_size) {
    const float* entity = (const float*)d_in[0];   // [NENT, C] f32
    const int*   eidx   = (const int*)d_in[1];     // [2, E] int32
    const int*   etype  = (const int*)d_in[2];     // [E]    int32
    float*       weight = (float*)d_in[3];         // [10, C] f32
    float*       out    = (float*)d_out;

    const int E = in_sizes[2];
    const int* head = eidx;
    const int* tail = eidx + E;

    // One-time CSR build
    k_init<<<128, 256>>>();
    k_hist<<<(E + 255) / 256, 256>>>(head, E);
    k_scan<<<1, 1024>>>();
    k_scatter<<<(E + 255) / 256, 256>>>(head, tail, etype, E);

    const float4* ent4  = (const float4*)entity;
    const float4* w4    = (const float4*)weight;
    float4*       o4    = (float4*)out;
    float4*       emb4  = (float4*)g_emb;
    float4*       emb4b = (float4*)g_emb2;

    const int nblocks = (NENT + 7) / 8;    // warp per entity, 8 warps/block

    // hop 1: entity -> g_emb   (residual base = entity, initializes out)
    k_hop<<<nblocks, 256>>>(ent4, ent4, o4, emb4, w4);
    // hop 2: g_emb -> g_emb2   (double-buffered; residual in-place on out)
    k_hop<<<nblocks, 256>>>(emb4, o4, o4, emb4b, w4);
    // hop 3: reads g_emb2, no emb write
    k_hop<<<nblocks, 256>>>(emb4b, o4, o4, nullptr, w4);
}

// round 8
// speedup vs baseline: 1.0018x; 1.0018x over previous
#include <cuda_runtime.h>

static constexpr int NENT = 50000;
static constexpr int CC   = 128;      // channels
static constexpr int C4   = 32;       // float4 per row
static constexpr int NRELM1 = 10;     // N_REL - 1
static constexpr int MAXE = 1700000;  // >= N_EDGES

// Scratch (no cudaMalloc allowed)
__device__ __align__(16) float g_emb [(size_t)NENT * CC];
__device__ __align__(16) float g_emb2[(size_t)NENT * CC];
__device__ int      g_hist[NENT];
__device__ int      g_cur[NENT];
__device__ int      g_off[NENT + 1];
__device__ unsigned g_packed[MAXE];   // tail | (type-1)<<20, head-sorted

// ---------------------------------------------------------------------------
__global__ void k_init() {
    const int stride = gridDim.x * blockDim.x;
    for (int j = blockIdx.x * blockDim.x + threadIdx.x; j < NENT; j += stride) {
        g_hist[j] = 0;
        g_cur[j]  = 0;
    }
}

__global__ void k_hist(const int* __restrict__ head, int E) {
    int i = blockIdx.x * blockDim.x + threadIdx.x;
    if (i < E) atomicAdd(&g_hist[head[i]], 1);
}

// Exclusive prefix scan of g_hist -> g_off (single block, 1024 threads)
__global__ void k_scan() {
    __shared__ int warpsum[32];
    __shared__ int warpoff[32];
    __shared__ int s_run;
    const int tid  = threadIdx.x;
    const int lane = tid & 31;
    const int wid  = tid >> 5;
    if (tid == 0) s_run = 0;
    __syncthreads();

    for (int base = 0; base < NENT; base += 1024) {
        int v = (base + tid < NENT) ? g_hist[base + tid] : 0;
        int x = v;
        #pragma unroll
        for (int o = 1; o < 32; o <<= 1) {
            int y = __shfl_up_sync(0xffffffffu, x, o);
            if (lane >= o) x += y;
        }
        if (lane == 31) warpsum[wid] = x;
        __syncthreads();
        if (wid == 0) {
            int w = warpsum[lane];
            int xi = w;
            #pragma unroll
            for (int o = 1; o < 32; o <<= 1) {
                int y = __shfl_up_sync(0xffffffffu, xi, o);
                if (lane >= o) xi += y;
            }
            warpoff[lane] = xi - w;   // exclusive warp offset
        }
        __syncthreads();
        int incl = x + warpoff[wid];
        int run  = s_run;
        if (base + tid < NENT) g_off[base + tid] = run + incl - v;
        __syncthreads();
        if (tid == 1023) s_run = run + incl;
        __syncthreads();
    }
    if (threadIdx.x == 0) g_off[NENT] = s_run;
}

__global__ void k_scatter(const int* __restrict__ head,
                          const int* __restrict__ tail,
                          const int* __restrict__ etype, int E) {
    int i = blockIdx.x * blockDim.x + threadIdx.x;
    if (i < E) {
        int h   = head[i];
        int pos = g_off[h] + atomicAdd(&g_cur[h], 1);
        g_packed[pos] = (unsigned)tail[i] | ((unsigned)(etype[i] - 1) << 20);
    }
}

// ---------------------------------------------------------------------------
// Fused hop: warp per head entity. No SHFL in the hot loop; 4-edge software
// pipeline so 4 row-gather LDG.128s are in flight per warp.
//   acc = sum_{edges of head} emb_in[tail] * w[type]   (registers)
//   n   = acc / max(||acc||, eps)    (degree divide elided: scale-invariant)
//   emb_out = n (if non-null);  out = resid_in + n
// emb_in and emb_out must be DISTINCT buffers.
// ---------------------------------------------------------------------------
__global__ void __launch_bounds__(256)
k_hop(const float4* __restrict__ emb_in,
      const float4* __restrict__ resid_in,
      float4*       __restrict__ out4,
      float4*       __restrict__ emb_out,   // may be null
      const float4* __restrict__ w4) {
    __shared__ float4 sw[NRELM1 * C4];   // 5 KB relation table
    for (int i = threadIdx.x; i < NRELM1 * C4; i += blockDim.x) sw[i] = w4[i];
    __syncthreads();

    const int warp = (blockIdx.x * blockDim.x + threadIdx.x) >> 5;
    const int lane = threadIdx.x & 31;
    if (warp >= NENT) return;

    const int s = g_off[warp];
    const int e = g_off[warp + 1];
    const int deg  = e - s;
    const int main_end = s + (deg & ~3);

    float4 acc = make_float4(0.f, 0.f, 0.f, 0.f);

    #pragma unroll 1
    for (int k = s; k < main_end; k += 4) {
        // broadcast loads (all lanes same address -> 1 request each)
        const unsigned p0 = g_packed[k + 0];
        const unsigned p1 = g_packed[k + 1];
        const unsigned p2 = g_packed[k + 2];
        const unsigned p3 = g_packed[k + 3];

        // 4 independent row gathers in flight
        const float4 ev0 = emb_in[(long)(p0 & 0xFFFFFu) * C4 + lane];
        const float4 ev1 = emb_in[(long)(p1 & 0xFFFFFu) * C4 + lane];
        const float4 ev2 = emb_in[(long)(p2 & 0xFFFFFu) * C4 + lane];
        const float4 ev3 = emb_in[(long)(p3 & 0xFFFFFu) * C4 + lane];

        const float4 r0 = sw[(p0 >> 20) * C4 + lane];
        const float4 r1 = sw[(p1 >> 20) * C4 + lane];
        const float4 r2 = sw[(p2 >> 20) * C4 + lane];
        const float4 r3 = sw[(p3 >> 20) * C4 + lane];

        acc.x += ev0.x * r0.x; acc.y += ev0.y * r0.y;
        acc.z += ev0.z * r0.z; acc.w += ev0.w * r0.w;
        acc.x += ev1.x * r1.x; acc.y += ev1.y * r1.y;
        acc.z += ev1.z * r1.z; acc.w += ev1.w * r1.w;
        acc.x += ev2.x * r2.x; acc.y += ev2.y * r2.y;
        acc.z += ev2.z * r2.z; acc.w += ev2.w * r2.w;
        acc.x += ev3.x * r3.x; acc.y += ev3.y * r3.y;
        acc.z += ev3.z * r3.z; acc.w += ev3.w * r3.w;
    }
    // tail (<= 3 edges)
    #pragma unroll 1
    for (int k = main_end; k < e; k++) {
        const unsigned p = g_packed[k];
        const float4 ev = emb_in[(long)(p & 0xFFFFFu) * C4 + lane];
        const float4 r  = sw[(p >> 20) * C4 + lane];
        acc.x += ev.x * r.x; acc.y += ev.y * r.y;
        acc.z += ev.z * r.z; acc.w += ev.w * r.w;
    }

    float ss = acc.x * acc.x + acc.y * acc.y + acc.z * acc.z + acc.w * acc.w;
    #pragma unroll
    for (int o = 16; o > 0; o >>= 1)
        ss += __shfl_xor_sync(0xffffffffu, ss, o);

    const float inv = 1.0f / fmaxf(sqrtf(ss), 1e-12f);
    const float4 n4 = make_float4(acc.x * inv, acc.y * inv,
                                  acc.z * inv, acc.w * inv);

    const long idx = (long)warp * C4 + lane;
    if (emb_out) emb_out[idx] = n4;
    const float4 b = resid_in[idx];
    out4[idx] = make_float4(b.x + n4.x, b.y + n4.y, b.z + n4.z, b.w + n4.w);
}

// ---------------------------------------------------------------------------
extern "C" void kernel_launch(void* const* d_in, const int* in_sizes, int n_in,
                              void* d_out, int out_size) {
    const float* entity = (const float*)d_in[0];   // [NENT, C] f32
    const int*   eidx   = (const int*)d_in[1];     // [2, E] int32
    const int*   etype  = (const int*)d_in[2];     // [E]    int32
    float*       weight = (float*)d_in[3];         // [10, C] f32
    float*       out    = (float*)d_out;

    const int E = in_sizes[2];
    const int* head = eidx;
    const int* tail = eidx + E;

    // One-time CSR build
    k_init<<<128, 256>>>();
    k_hist<<<(E + 255) / 256, 256>>>(head, E);
    k_scan<<<1, 1024>>>();
    k_scatter<<<(E + 255) / 256, 256>>>(head, tail, etype, E);

    const float4* ent4  = (const float4*)entity;
    const float4* w4    = (const float4*)weight;
    float4*       o4    = (float4*)out;
    float4*       emb4  = (float4*)g_emb;
    float4*       emb4b = (float4*)g_emb2;

    const int nblocks = (NENT + 7) / 8;    // warp per entity, 8 warps/block

    // hop 1: entity -> g_emb   (residual base = entity, initializes out)
    k_hop<<<nblocks, 256>>>(ent4, ent4, o4, emb4, w4);
    // hop 2: g_emb -> g_emb2   (double-buffered)
    k_hop<<<nblocks, 256>>>(emb4, o4, o4, emb4b, w4);
    // hop 3: reads g_emb2, no emb write
    k_hop<<<nblocks, 256>>>(emb4b, o4, o4, nullptr, w4);
}

// round 9
// speedup vs baseline: 30.4738x; 30.4182x over previous
#include <cuda_runtime.h>

static constexpr int NENT = 50000;
static constexpr int CC   = 128;      // channels
static constexpr int C4   = 32;       // float4 per row
static constexpr int NRELM1 = 10;     // N_REL - 1
static constexpr int MAXE = 1700000;  // >= N_EDGES

// Scratch (no cudaMalloc allowed). NEVER pass these symbols from host code —
// on GB300 the host-side shadow address is ATS-coherent and routes all traffic
// over NVLink-C2C at ~200 GB/s. Resolve them INSIDE kernels only.
__device__ __align__(16) float g_emb [(size_t)NENT * CC];
__device__ __align__(16) float g_emb2[(size_t)NENT * CC];
__device__ int      g_hist[NENT];
__device__ int      g_cur[NENT];
__device__ int      g_off[NENT + 1];
__device__ unsigned g_packed[MAXE];   // tail | (type-1)<<20, head-sorted

// ---------------------------------------------------------------------------
__global__ void k_init() {
    const int stride = gridDim.x * blockDim.x;
    for (int j = blockIdx.x * blockDim.x + threadIdx.x; j < NENT; j += stride) {
        g_hist[j] = 0;
        g_cur[j]  = 0;
    }
}

__global__ void k_hist(const int* __restrict__ head, int E) {
    int i = blockIdx.x * blockDim.x + threadIdx.x;
    if (i < E) atomicAdd(&g_hist[head[i]], 1);
}

// Exclusive prefix scan of g_hist -> g_off (single block, 1024 threads)
__global__ void k_scan() {
    __shared__ int warpsum[32];
    __shared__ int warpoff[32];
    __shared__ int s_run;
    const int tid  = threadIdx.x;
    const int lane = tid & 31;
    const int wid  = tid >> 5;
    if (tid == 0) s_run = 0;
    __syncthreads();

    for (int base = 0; base < NENT; base += 1024) {
        int v = (base + tid < NENT) ? g_hist[base + tid] : 0;
        int x = v;
        #pragma unroll
        for (int o = 1; o < 32; o <<= 1) {
            int y = __shfl_up_sync(0xffffffffu, x, o);
            if (lane >= o) x += y;
        }
        if (lane == 31) warpsum[wid] = x;
        __syncthreads();
        if (wid == 0) {
            int w = warpsum[lane];
            int xi = w;
            #pragma unroll
            for (int o = 1; o < 32; o <<= 1) {
                int y = __shfl_up_sync(0xffffffffu, xi, o);
                if (lane >= o) xi += y;
            }
            warpoff[lane] = xi - w;   // exclusive warp offset
        }
        __syncthreads();
        int incl = x + warpoff[wid];
        int run  = s_run;
        if (base + tid < NENT) g_off[base + tid] = run + incl - v;
        __syncthreads();
        if (tid == 1023) s_run = run + incl;
        __syncthreads();
    }
    if (threadIdx.x == 0) g_off[NENT] = s_run;
}

__global__ void k_scatter(const int* __restrict__ head,
                          const int* __restrict__ tail,
                          const int* __restrict__ etype, int E) {
    int i = blockIdx.x * blockDim.x + threadIdx.x;
    if (i < E) {
        int h   = head[i];
        int pos = g_off[h] + atomicAdd(&g_cur[h], 1);
        g_packed[pos] = (unsigned)tail[i] | ((unsigned)(etype[i] - 1) << 20);
    }
}

// ---------------------------------------------------------------------------
// Fused hop: warp per head entity. 4-edge software pipeline (4 gather LDG.128
// in flight). Buffers selected by small int INSIDE the kernel (device symbols
// must not cross the host launch boundary).
//   src: 0 = ext_in (harness buffer), 1 = g_emb, 2 = g_emb2
//   dst: 0 = none,                    1 = g_emb, 2 = g_emb2
//   acc = sum emb_in[tail]*w[type]; n = acc/max(||acc||,eps);
//   emb_dst = n; out = resid_in + n
// ---------------------------------------------------------------------------
__global__ void __launch_bounds__(256)
k_hop(const float4* __restrict__ ext_in, int src, int dst,
      const float4* __restrict__ resid_in,
      float4*       __restrict__ out4,
      const float4* __restrict__ w4) {
    __shared__ float4 sw[NRELM1 * C4];   // 5 KB relation table
    for (int i = threadIdx.x; i < NRELM1 * C4; i += blockDim.x) sw[i] = w4[i];
    __syncthreads();

    const int warp = (blockIdx.x * blockDim.x + threadIdx.x) >> 5;
    const int lane = threadIdx.x & 31;
    if (warp >= NENT) return;

    const float4* emb_in =
        (src == 0) ? ext_in :
        (src == 1) ? reinterpret_cast<const float4*>(g_emb)
                   : reinterpret_cast<const float4*>(g_emb2);

    const int s = g_off[warp];
    const int e = g_off[warp + 1];
    const int main_end = s + ((e - s) & ~3);

    float4 acc = make_float4(0.f, 0.f, 0.f, 0.f);

    #pragma unroll 1
    for (int k = s; k < main_end; k += 4) {
        const unsigned p0 = g_packed[k + 0];
        const unsigned p1 = g_packed[k + 1];
        const unsigned p2 = g_packed[k + 2];
        const unsigned p3 = g_packed[k + 3];

        const float4 ev0 = emb_in[(p0 & 0xFFFFFu) * C4 + lane];
        const float4 ev1 = emb_in[(p1 & 0xFFFFFu) * C4 + lane];
        const float4 ev2 = emb_in[(p2 & 0xFFFFFu) * C4 + lane];
        const float4 ev3 = emb_in[(p3 & 0xFFFFFu) * C4 + lane];

        const float4 r0 = sw[(p0 >> 20) * C4 + lane];
        const float4 r1 = sw[(p1 >> 20) * C4 + lane];
        const float4 r2 = sw[(p2 >> 20) * C4 + lane];
        const float4 r3 = sw[(p3 >> 20) * C4 + lane];

        acc.x += ev0.x * r0.x; acc.y += ev0.y * r0.y;
        acc.z += ev0.z * r0.z; acc.w += ev0.w * r0.w;
        acc.x += ev1.x * r1.x; acc.y += ev1.y * r1.y;
        acc.z += ev1.z * r1.z; acc.w += ev1.w * r1.w;
        acc.x += ev2.x * r2.x; acc.y += ev2.y * r2.y;
        acc.z += ev2.z * r2.z; acc.w += ev2.w * r2.w;
        acc.x += ev3.x * r3.x; acc.y += ev3.y * r3.y;
        acc.z += ev3.z * r3.z; acc.w += ev3.w * r3.w;
    }
    #pragma unroll 1
    for (int k = main_end; k < e; k++) {
        const unsigned p = g_packed[k];
        const float4 ev = emb_in[(p & 0xFFFFFu) * C4 + lane];
        const float4 r  = sw[(p >> 20) * C4 + lane];
        acc.x += ev.x * r.x; acc.y += ev.y * r.y;
        acc.z += ev.z * r.z; acc.w += ev.w * r.w;
    }

    float ss = acc.x * acc.x + acc.y * acc.y + acc.z * acc.z + acc.w * acc.w;
    #pragma unroll
    for (int o = 16; o > 0; o >>= 1)
        ss += __shfl_xor_sync(0xffffffffu, ss, o);

    const float inv = 1.0f / fmaxf(sqrtf(ss), 1e-12f);
    const float4 n4 = make_float4(acc.x * inv, acc.y * inv,
                                  acc.z * inv, acc.w * inv);

    const int idx = warp * C4 + lane;
    if (dst == 1)      reinterpret_cast<float4*>(g_emb)[idx]  = n4;
    else if (dst == 2) reinterpret_cast<float4*>(g_emb2)[idx] = n4;
    const float4 b = resid_in[idx];
    out4[idx] = make_float4(b.x + n4.x, b.y + n4.y, b.z + n4.z, b.w + n4.w);
}

// ---------------------------------------------------------------------------
extern "C" void kernel_launch(void* const* d_in, const int* in_sizes, int n_in,
                              void* d_out, int out_size) {
    const float* entity = (const float*)d_in[0];   // [NENT, C] f32
    const int*   eidx   = (const int*)d_in[1];     // [2, E] int32
    const int*   etype  = (const int*)d_in[2];     // [E]    int32
    const float* weight = (const float*)d_in[3];   // [10, C] f32
    float*       out    = (float*)d_out;

    const int E = in_sizes[2];
    const int* head = eidx;
    const int* tail = eidx + E;

    // One-time CSR build (all device-symbol state touched in-kernel only)
    k_init<<<128, 256>>>();
    k_hist<<<(E + 255) / 256, 256>>>(head, E);
    k_scan<<<1, 1024>>>();
    k_scatter<<<(E + 255) / 256, 256>>>(head, tail, etype, E);

    const float4* ent4 = (const float4*)entity;
    const float4* w4   = (const float4*)weight;
    float4*       o4   = (float4*)out;

    const int nblocks = (NENT + 7) / 8;    // warp per entity, 8 warps/block

    // hop 1: entity -> g_emb   (residual base = entity, initializes out)
    k_hop<<<nblocks, 256>>>(ent4, /*src=*/0, /*dst=*/1, ent4, o4, w4);
    // hop 2: g_emb -> g_emb2   (residual in-place on out)
    k_hop<<<nblocks, 256>>>(ent4, /*src=*/1, /*dst=*/2, o4, o4, w4);
    // hop 3: reads g_emb2, no emb write
    k_hop<<<nblocks, 256>>>(ent4, /*src=*/2, /*dst=*/0, o4, o4, w4);
}

// round 13
// speedup vs baseline: 33.0249x; 1.0837x over previous
#include <cuda_runtime.h>
#include <cuda_bf16.h>

static constexpr int NENT = 50000;
static constexpr int CC   = 128;      // channels
static constexpr int C4   = 32;       // float4 per row (fp32 path)
static constexpr int NRELM1 = 10;     // N_REL - 1
static constexpr int MAXE = 1700000;  // >= N_EDGES

// Scratch (no cudaMalloc allowed). NEVER pass these symbols from host code —
// on GB300 the host-side shadow address is ATS-coherent and routes traffic
// over NVLink-C2C at ~200 GB/s. Resolve them INSIDE kernels only.
// Intermediate hop embeddings stored as bf16 (uint2 = 4 channels per lane).
__device__ __align__(16) uint2 g_embh [(size_t)NENT * 32];
__device__ __align__(16) uint2 g_embh2[(size_t)NENT * 32];
__device__ int      g_hist[NENT];
__device__ int      g_cur[NENT];
__device__ int      g_off[NENT + 1];
__device__ unsigned g_packed[MAXE];   // tail | (type-1)<<20, head-sorted

// ---------------------------------------------------------------------------
__global__ void k_init() {
    const int stride = gridDim.x * blockDim.x;
    for (int j = blockIdx.x * blockDim.x + threadIdx.x; j < NENT; j += stride) {
        g_hist[j] = 0;
        g_cur[j]  = 0;
    }
}

__global__ void k_hist(const int* __restrict__ head, int E) {
    int i = blockIdx.x * blockDim.x + threadIdx.x;
    if (i < E) atomicAdd(&g_hist[head[i]], 1);
}

// Exclusive prefix scan of g_hist -> g_off (single block, 1024 threads)
__global__ void k_scan() {
    __shared__ int warpsum[32];
    __shared__ int warpoff[32];
    __shared__ int s_run;
    const int tid  = threadIdx.x;
    const int lane = tid & 31;
    const int wid  = tid >> 5;
    if (tid == 0) s_run = 0;
    __syncthreads();

    for (int base = 0; base < NENT; base += 1024) {
        int v = (base + tid < NENT) ? g_hist[base + tid] : 0;
        int x = v;
        #pragma unroll
        for (int o = 1; o < 32; o <<= 1) {
            int y = __shfl_up_sync(0xffffffffu, x, o);
            if (lane >= o) x += y;
        }
        if (lane == 31) warpsum[wid] = x;
        __syncthreads();
        if (wid == 0) {
            int w = warpsum[lane];
            int xi = w;
            #pragma unroll
            for (int o = 1; o < 32; o <<= 1) {
                int y = __shfl_up_sync(0xffffffffu, xi, o);
                if (lane >= o) xi += y;
            }
            warpoff[lane] = xi - w;   // exclusive warp offset
        }
        __syncthreads();
        int incl = x + warpoff[wid];
        int run  = s_run;
        if (base + tid < NENT) g_off[base + tid] = run + incl - v;
        __syncthreads();
        if (tid == 1023) s_run = run + incl;
        __syncthreads();
    }
    if (threadIdx.x == 0) g_off[NENT] = s_run;
}

__global__ void k_scatter(const int* __restrict__ head,
                          const int* __restrict__ tail,
                          const int* __restrict__ etype, int E) {
    int i = blockIdx.x * blockDim.x + threadIdx.x;
    if (i < E) {
        int h   = head[i];
        int pos = g_off[h] + atomicAdd(&g_cur[h], 1);
        g_packed[pos] = (unsigned)tail[i] | ((unsigned)(etype[i] - 1) << 20);
    }
}

// ---------------------------------------------------------------------------
__device__ __forceinline__ float4 ld_row_bf16(const uint2* __restrict__ base,
                                              unsigned t, int lane) {
    const uint2 u = base[t * 32 + lane];
    const __nv_bfloat162 lo = *reinterpret_cast<const __nv_bfloat162*>(&u.x);
    const __nv_bfloat162 hi = *reinterpret_cast<const __nv_bfloat162*>(&u.y);
    const float2 f0 = __bfloat1622float2(lo);
    const float2 f1 = __bfloat1622float2(hi);
    return make_float4(f0.x, f0.y, f1.x, f1.y);
}

// ---------------------------------------------------------------------------
// Fused hop: warp per head entity. 4-edge software pipeline.
// SRC_F32: hop 1 gathers the fp32 input tensor; hops 2/3 gather bf16
// intermediates (halved gather traffic — the LTS-cap bottleneck).
//   src: 1 = g_embh, 2 = g_embh2 (ignored when SRC_F32)
//   dst: 0 = none, 1 = g_embh, 2 = g_embh2 (bf16 store)
//   acc = sum emb_in[tail]*w[type]; n = acc/max(||acc||,eps)
//        (degree divide elided: normalize is scale-invariant)
//   emb_dst = bf16(n); out = resid_in + n
// ---------------------------------------------------------------------------
template <bool SRC_F32>
__global__ void __launch_bounds__(256)
k_hop(const float4* __restrict__ ext_in, int src, int dst,
      const float4* __restrict__ resid_in,
      float4*       __restrict__ out4,
      const float4* __restrict__ w4) {
    __shared__ float4 sw[NRELM1 * C4];   // 5 KB relation table
    for (int i = threadIdx.x; i < NRELM1 * C4; i += blockDim.x) sw[i] = w4[i];
    __syncthreads();

    const int warp = (blockIdx.x * blockDim.x + threadIdx.x) >> 5;
    const int lane = threadIdx.x & 31;
    if (warp >= NENT) return;

    const uint2* embh_in = (src == 1) ? g_embh : g_embh2;

    const int s = g_off[warp];
    const int e = g_off[warp + 1];
    const int main_end = s + ((e - s) & ~3);

    float4 acc = make_float4(0.f, 0.f, 0.f, 0.f);

    #pragma unroll 1
    for (int k = s; k < main_end; k += 4) {
        const unsigned p0 = g_packed[k + 0];
        const unsigned p1 = g_packed[k + 1];
        const unsigned p2 = g_packed[k + 2];
        const unsigned p3 = g_packed[k + 3];

        float4 ev0, ev1, ev2, ev3;
        if (SRC_F32) {
            ev0 = ext_in[(p0 & 0xFFFFFu) * C4 + lane];
            ev1 = ext_in[(p1 & 0xFFFFFu) * C4 + lane];
            ev2 = ext_in[(p2 & 0xFFFFFu) * C4 + lane];
            ev3 = ext_in[(p3 & 0xFFFFFu) * C4 + lane];
        } else {
            ev0 = ld_row_bf16(embh_in, p0 & 0xFFFFFu, lane);
            ev1 = ld_row_bf16(embh_in, p1 & 0xFFFFFu, lane);
            ev2 = ld_row_bf16(embh_in, p2 & 0xFFFFFu, lane);
            ev3 = ld_row_bf16(embh_in, p3 & 0xFFFFFu, lane);
        }

        const float4 r0 = sw[(p0 >> 20) * C4 + lane];
        const float4 r1 = sw[(p1 >> 20) * C4 + lane];
        const float4 r2 = sw[(p2 >> 20) * C4 + lane];
        const float4 r3 = sw[(p3 >> 20) * C4 + lane];

        acc.x += ev0.x * r0.x; acc.y += ev0.y * r0.y;
        acc.z += ev0.z * r0.z; acc.w += ev0.w * r0.w;
        acc.x += ev1.x * r1.x; acc.y += ev1.y * r1.y;
        acc.z += ev1.z * r1.z; acc.w += ev1.w * r1.w;
        acc.x += ev2.x * r2.x; acc.y += ev2.y * r2.y;
        acc.z += ev2.z * r2.z; acc.w += ev2.w * r2.w;
        acc.x += ev3.x * r3.x; acc.y += ev3.y * r3.y;
        acc.z += ev3.z * r3.z; acc.w += ev3.w * r3.w;
    }
    #pragma unroll 1
    for (int k = main_end; k < e; k++) {
        const unsigned p = g_packed[k];
        const float4 ev = SRC_F32 ? ext_in[(p & 0xFFFFFu) * C4 + lane]
                                  : ld_row_bf16(embh_in, p & 0xFFFFFu, lane);
        const float4 r  = sw[(p >> 20) * C4 + lane];
        acc.x += ev.x * r.x; acc.y += ev.y * r.y;
        acc.z += ev.z * r.z; acc.w += ev.w * r.w;
    }

    float ss = acc.x * acc.x + acc.y * acc.y + acc.z * acc.z + acc.w * acc.w;
    #pragma unroll
    for (int o = 16; o > 0; o >>= 1)
        ss += __shfl_xor_sync(0xffffffffu, ss, o);

    const float inv = 1.0f / fmaxf(sqrtf(ss), 1e-12f);
    const float4 n4 = make_float4(acc.x * inv, acc.y * inv,
                                  acc.z * inv, acc.w * inv);

    if (dst != 0) {
        const __nv_bfloat162 lo = __floats2bfloat162_rn(n4.x, n4.y);
        const __nv_bfloat162 hi = __floats2bfloat162_rn(n4.z, n4.w);
        uint2 u;
        u.x = *reinterpret_cast<const unsigned*>(&lo);
        u.y = *reinterpret_cast<const unsigned*>(&hi);
        (dst == 1 ? g_embh : g_embh2)[warp * 32 + lane] = u;
    }

    const int idx = warp * C4 + lane;
    const float4 b = resid_in[idx];
    out4[idx] = make_float4(b.x + n4.x, b.y + n4.y, b.z + n4.z, b.w + n4.w);
}

// ---------------------------------------------------------------------------
extern "C" void kernel_launch(void* const* d_in, const int* in_sizes, int n_in,
                              void* d_out, int out_size) {
    const float* entity = (const float*)d_in[0];   // [NENT, C] f32
    const int*   eidx   = (const int*)d_in[1];     // [2, E] int32
    const int*   etype  = (const int*)d_in[2];     // [E]    int32
    const float* weight = (const float*)d_in[3];   // [10, C] f32
    float*       out    = (float*)d_out;

    const int E = in_sizes[2];
    const int* head = eidx;
    const int* tail = eidx + E;

    // One-time CSR build (device-symbol state touched in-kernel only)
    k_init<<<128, 256>>>();
    k_hist<<<(E + 255) / 256, 256>>>(head, E);
    k_scan<<<1, 1024>>>();
    k_scatter<<<(E + 255) / 256, 256>>>(head, tail, etype, E);

    const float4* ent4 = (const float4*)entity;
    const float4* w4   = (const float4*)weight;
    float4*       o4   = (float4*)out;

    const int nblocks = (NENT + 7) / 8;    // warp per entity, 8 warps/block

    // hop 1: fp32 entity -> bf16 g_embh   (residual base = entity, inits out)
    k_hop<true ><<<nblocks, 256>>>(ent4, /*src=*/0, /*dst=*/1, ent4, o4, w4);
    // hop 2: bf16 g_embh -> bf16 g_embh2  (residual in-place on out)
    k_hop<false><<<nblocks, 256>>>(ent4, /*src=*/1, /*dst=*/2, o4, o4, w4);
    // hop 3: reads bf16 g_embh2, no emb write
    k_hop<false><<<nblocks, 256>>>(ent4, /*src=*/2, /*dst=*/0, o4, o4, w4);
}

// round 16
// speedup vs baseline: 38.0842x; 1.1532x over previous
#include <cuda_runtime.h>
#include <cuda_bf16.h>

static constexpr int NENT = 50000;
static constexpr int CC   = 128;      // channels
static constexpr int C4   = 32;       // float4 per row (fp32 path)
static constexpr int NRELM1 = 10;     // N_REL - 1
static constexpr int MAXE = 1700000;  // >= N_EDGES
static constexpr int SCAN_BS = 1024;
static constexpr int NBLK = (NENT + SCAN_BS - 1) / SCAN_BS;  // 49

// Scratch (no cudaMalloc allowed). NEVER pass these symbols from host code —
// on GB300 the host-side shadow address is ATS-coherent and routes traffic
// over NVLink-C2C at ~200 GB/s. Resolve them INSIDE kernels only.
// Embeddings stored as bf16 (uint2 = 4 channels per lane).
__device__ __align__(16) uint2 g_embh [(size_t)NENT * 32];   // buffer A
__device__ __align__(16) uint2 g_embh2[(size_t)NENT * 32];   // buffer B
__device__ int      g_hist[NENT];
__device__ int      g_cur[NENT];
__device__ int      g_off[NENT + 1];
__device__ int      g_bsum[NBLK];
__device__ int      g_boff[NBLK];
__device__ unsigned g_packed[MAXE];   // tail | (type-1)<<20, head-sorted

// ---------------------------------------------------------------------------
__global__ void k_init() {
    const int stride = gridDim.x * blockDim.x;
    for (int j = blockIdx.x * blockDim.x + threadIdx.x; j < NENT; j += stride) {
        g_hist[j] = 0;
        g_cur[j]  = 0;
    }
}

__global__ void k_hist(const int* __restrict__ head, int E) {
    int i = blockIdx.x * blockDim.x + threadIdx.x;
    if (i < E) atomicAdd(&g_hist[head[i]], 1);
}

// Convert fp32 entity table -> bf16 buffer A (halves hop-1 gather traffic)
__global__ void k_cvt(const float4* __restrict__ in4) {
    int i = blockIdx.x * blockDim.x + threadIdx.x;
    if (i < NENT * 32) {
        const float4 v = in4[i];
        const __nv_bfloat162 lo = __floats2bfloat162_rn(v.x, v.y);
        const __nv_bfloat162 hi = __floats2bfloat162_rn(v.z, v.w);
        uint2 u;
        u.x = *reinterpret_cast<const unsigned*>(&lo);
        u.y = *reinterpret_cast<const unsigned*>(&hi);
        g_embh[i] = u;
    }
}

// ---- 3-phase parallel exclusive scan of g_hist -> g_off -------------------
// Phase A: each block scans its 1024-chunk, writes block-local exclusive scan
// to g_off and its total to g_bsum.
__global__ void k_scanA() {
    __shared__ int warpsum[32];
    __shared__ int warpoff[32];
    const int tid  = threadIdx.x;
    const int lane = tid & 31;
    const int wid  = tid >> 5;
    const int i    = blockIdx.x * SCAN_BS + tid;

    int v = (i < NENT) ? g_hist[i] : 0;
    int x = v;
    #pragma unroll
    for (int o = 1; o < 32; o <<= 1) {
        int y = __shfl_up_sync(0xffffffffu, x, o);
        if (lane >= o) x += y;
    }
    if (lane == 31) warpsum[wid] = x;
    __syncthreads();
    if (wid == 0) {
        int w  = warpsum[lane];
        int xi = w;
        #pragma unroll
        for (int o = 1; o < 32; o <<= 1) {
            int y = __shfl_up_sync(0xffffffffu, xi, o);
            if (lane >= o) xi += y;
        }
        warpoff[lane] = xi - w;
    }
    __syncthreads();
    const int incl = x + warpoff[wid];
    if (i < NENT) g_off[i] = incl - v;            // block-local exclusive
    if (tid == SCAN_BS - 1) g_bsum[blockIdx.x] = incl;
}

// Phase B: one warp scans the NBLK (<=64) block totals -> exclusive g_boff.
__global__ void k_scanB() {
    const int lane = threadIdx.x;   // 32 threads
    int v0 = (lane < NBLK) ? g_bsum[lane] : 0;
    int x0 = v0;
    #pragma unroll
    for (int o = 1; o < 32; o <<= 1) {
        int y = __shfl_up_sync(0xffffffffu, x0, o);
        if (lane >= o) x0 += y;
    }
    if (lane < NBLK) g_boff[lane] = x0 - v0;
    const int tot0 = __shfl_sync(0xffffffffu, x0, 31);

    const int j = 32 + lane;
    int v1 = (j < NBLK) ? g_bsum[j] : 0;
    int x1 = v1;
    #pragma unroll
    for (int o = 1; o < 32; o <<= 1) {
        int y = __shfl_up_sync(0xffffffffu, x1, o);
        if (lane >= o) x1 += y;
    }
    if (j < NBLK) g_boff[j] = tot0 + x1 - v1;
}

// Phase C: add block offsets; set sentinel.
__global__ void k_scanC(int E) {
    int i = blockIdx.x * blockDim.x + threadIdx.x;
    if (i < NENT) g_off[i] += g_boff[i >> 10];
    if (i == 0)   g_off[NENT] = E;
}

__global__ void k_scatter(const int* __restrict__ head,
                          const int* __restrict__ tail,
                          const int* __restrict__ etype, int E) {
    int i = blockIdx.x * blockDim.x + threadIdx.x;
    if (i < E) {
        int h   = head[i];
        int pos = g_off[h] + atomicAdd(&g_cur[h], 1);
        g_packed[pos] = (unsigned)tail[i] | ((unsigned)(etype[i] - 1) << 20);
    }
}

// ---------------------------------------------------------------------------
__device__ __forceinline__ float4 ld_row_bf16(const uint2* __restrict__ base,
                                              unsigned t, int lane) {
    const uint2 u = base[t * 32 + lane];
    const __nv_bfloat162 lo = *reinterpret_cast<const __nv_bfloat162*>(&u.x);
    const __nv_bfloat162 hi = *reinterpret_cast<const __nv_bfloat162*>(&u.y);
    const float2 f0 = __bfloat1622float2(lo);
    const float2 f1 = __bfloat1622float2(hi);
    return make_float4(f0.x, f0.y, f1.x, f1.y);
}

// ---------------------------------------------------------------------------
// Fused hop: warp per head entity; 4-edge software pipeline; bf16 gathers.
//   src: 1 = A (g_embh), 2 = B (g_embh2)
//   dst: 0 = none, 1 = A, 2 = B
//   acc = sum emb_in[tail]*w[type]; n = acc/max(||acc||,eps)
//        (degree divide elided: normalize is scale-invariant)
//   emb_dst = bf16(n); out = resid_in + n   (fp32)
// ---------------------------------------------------------------------------
__global__ void __launch_bounds__(256)
k_hop(int src, int dst,
      const float4* __restrict__ resid_in,
      float4*       __restrict__ out4,
      const float4* __restrict__ w4) {
    __shared__ float4 sw[NRELM1 * C4];   // 5 KB relation table
    for (int i = threadIdx.x; i < NRELM1 * C4; i += blockDim.x) sw[i] = w4[i];
    __syncthreads();

    const int warp = (blockIdx.x * blockDim.x + threadIdx.x) >> 5;
    const int lane = threadIdx.x & 31;
    if (warp >= NENT) return;

    const uint2* embh_in = (src == 1) ? g_embh : g_embh2;

    const int s = g_off[warp];
    const int e = g_off[warp + 1];
    const int main_end = s + ((e - s) & ~3);

    float4 acc = make_float4(0.f, 0.f, 0.f, 0.f);

    #pragma unroll 1
    for (int k = s; k < main_end; k += 4) {
        const unsigned p0 = g_packed[k + 0];
        const unsigned p1 = g_packed[k + 1];
        const unsigned p2 = g_packed[k + 2];
        const unsigned p3 = g_packed[k + 3];

        const float4 ev0 = ld_row_bf16(embh_in, p0 & 0xFFFFFu, lane);
        const float4 ev1 = ld_row_bf16(embh_in, p1 & 0xFFFFFu, lane);
        const float4 ev2 = ld_row_bf16(embh_in, p2 & 0xFFFFFu, lane);
        const float4 ev3 = ld_row_bf16(embh_in, p3 & 0xFFFFFu, lane);

        const float4 r0 = sw[(p0 >> 20) * C4 + lane];
        const float4 r1 = sw[(p1 >> 20) * C4 + lane];
        const float4 r2 = sw[(p2 >> 20) * C4 + lane];
        const float4 r3 = sw[(p3 >> 20) * C4 + lane];

        acc.x += ev0.x * r0.x; acc.y += ev0.y * r0.y;
        acc.z += ev0.z * r0.z; acc.w += ev0.w * r0.w;
        acc.x += ev1.x * r1.x; acc.y += ev1.y * r1.y;
        acc.z += ev1.z * r1.z; acc.w += ev1.w * r1.w;
        acc.x += ev2.x * r2.x; acc.y += ev2.y * r2.y;
        acc.z += ev2.z * r2.z; acc.w += ev2.w * r2.w;
        acc.x += ev3.x * r3.x; acc.y += ev3.y * r3.y;
        acc.z += ev3.z * r3.z; acc.w += ev3.w * r3.w;
    }
    #pragma unroll 1
    for (int k = main_end; k < e; k++) {
        const unsigned p = g_packed[k];
        const float4 ev = ld_row_bf16(embh_in, p & 0xFFFFFu, lane);
        const float4 r  = sw[(p >> 20) * C4 + lane];
        acc.x += ev.x * r.x; acc.y += ev.y * r.y;
        acc.z += ev.z * r.z; acc.w += ev.w * r.w;
    }

    float ss = acc.x * acc.x + acc.y * acc.y + acc.z * acc.z + acc.w * acc.w;
    #pragma unroll
    for (int o = 16; o > 0; o >>= 1)
        ss += __shfl_xor_sync(0xffffffffu, ss, o);

    const float inv = 1.0f / fmaxf(sqrtf(ss), 1e-12f);
    const float4 n4 = make_float4(acc.x * inv, acc.y * inv,
                                  acc.z * inv, acc.w * inv);

    if (dst != 0) {
        const __nv_bfloat162 lo = __floats2bfloat162_rn(n4.x, n4.y);
        const __nv_bfloat162 hi = __floats2bfloat162_rn(n4.z, n4.w);
        uint2 u;
        u.x = *reinterpret_cast<const unsigned*>(&lo);
        u.y = *reinterpret_cast<const unsigned*>(&hi);
        (dst == 1 ? g_embh : g_embh2)[warp * 32 + lane] = u;
    }

    const int idx = warp * C4 + lane;
    const float4 b = resid_in[idx];
    out4[idx] = make_float4(b.x + n4.x, b.y + n4.y, b.z + n4.z, b.w + n4.w);
}

// ---------------------------------------------------------------------------
extern "C" void kernel_launch(void* const* d_in, const int* in_sizes, int n_in,
                              void* d_out, int out_size) {
    const float* entity = (const float*)d_in[0];   // [NENT, C] f32
    const int*   eidx   = (const int*)d_in[1];     // [2, E] int32
    const int*   etype  = (const int*)d_in[2];     // [E]    int32
    const float* weight = (const float*)d_in[3];   // [10, C] f32
    float*       out    = (float*)d_out;

    const int E = in_sizes[2];
    const int* head = eidx;
    const int* tail = eidx + E;

    const float4* ent4 = (const float4*)entity;
    const float4* w4   = (const float4*)weight;
    float4*       o4   = (float4*)out;

    // One-time CSR build + input conversion (device symbols in-kernel only)
    k_init<<<128, 256>>>();
    k_cvt <<<(NENT * 32 + 255) / 256, 256>>>(ent4);
    k_hist<<<(E + 255) / 256, 256>>>(head, E);
    k_scanA<<<NBLK, SCAN_BS>>>();
    k_scanB<<<1, 32>>>();
    k_scanC<<<(NENT + 255) / 256, 256>>>(E);
    k_scatter<<<(E + 255) / 256, 256>>>(head, tail, etype, E);

    const int nblocks = (NENT + 7) / 8;    // warp per entity, 8 warps/block

    // hop 1: A -> B  (residual base = entity fp32, initializes out)
    k_hop<<<nblocks, 256>>>(/*src=*/1, /*dst=*/2, ent4, o4, w4);
    // hop 2: B -> A  (A dead after hop 1; residual in-place on out)
    k_hop<<<nblocks, 256>>>(/*src=*/2, /*dst=*/1, o4, o4, w4);
    // hop 3: reads A, no emb write
    k_hop<<<nblocks, 256>>>(/*src=*/1, /*dst=*/0, o4, o4, w4);
}